// round 1
// baseline (speedup 1.0000x reference)
#include <cuda_runtime.h>
#include <cstdint>

// Problem constants (fixed by reference)
#define Bz 2
#define Sz 2048
#define Dz 1024
#define Hz 16
#define HDz 64
#define Mz (Bz*Sz)          // 4096 rows

// -------------------- scratch (device globals; no allocation) --------------------
__device__ float g_q[Mz * Dz];
__device__ float g_k[Mz * Dz];
__device__ float g_v[Mz * Dz];
__device__ float g_ctx[Mz * Dz];

// ==================== SGEMM: C[M,N] = A[M,K] @ W[K,N] + bias[N] ====================
// 128x128x16 tiles, 256 threads, 8x8 micro-tiles.
__global__ __launch_bounds__(256) void sgemm_bias(
    const float* __restrict__ A, const float* __restrict__ W,
    const float* __restrict__ bias, float* __restrict__ C,
    int M, int N, int K)
{
    __shared__ float As[16][128];   // A transposed: As[k][m]
    __shared__ float Bs[16][128];   // Bs[k][n]

    const int tid = threadIdx.x;
    const int m0 = blockIdx.y * 128;
    const int n0 = blockIdx.x * 128;
    const int tr = tid >> 4;        // 0..15 -> rows tr*8..+7
    const int tc = tid & 15;        // 0..15 -> cols tc*8..+7

    float acc[8][8];
#pragma unroll
    for (int i = 0; i < 8; i++)
#pragma unroll
        for (int j = 0; j < 8; j++) acc[i][j] = 0.f;

    for (int k0 = 0; k0 < K; k0 += 16) {
        // load A tile (128 x 16) -> transposed store
#pragma unroll
        for (int it = 0; it < 2; it++) {
            int idx = tid + it * 256;            // 0..511
            int row = idx >> 2;                  // 0..127
            int k4  = (idx & 3) * 4;             // 0,4,8,12
            float4 a = *(const float4*)(A + (size_t)(m0 + row) * K + k0 + k4);
            As[k4 + 0][row] = a.x;
            As[k4 + 1][row] = a.y;
            As[k4 + 2][row] = a.z;
            As[k4 + 3][row] = a.w;
        }
        // load B tile (16 x 128)
#pragma unroll
        for (int it = 0; it < 2; it++) {
            int idx = tid + it * 256;
            int kr = idx >> 5;                   // 0..15
            int n4 = (idx & 31) * 4;             // 0..124
            *(float4*)(&Bs[kr][n4]) =
                *(const float4*)(W + (size_t)(k0 + kr) * N + n0 + n4);
        }
        __syncthreads();

#pragma unroll
        for (int k = 0; k < 16; k++) {
            float ar[8], br[8];
            *(float4*)(ar)     = *(const float4*)(&As[k][tr * 8]);
            *(float4*)(ar + 4) = *(const float4*)(&As[k][tr * 8 + 4]);
            *(float4*)(br)     = *(const float4*)(&Bs[k][tc * 8]);
            *(float4*)(br + 4) = *(const float4*)(&Bs[k][tc * 8 + 4]);
#pragma unroll
            for (int i = 0; i < 8; i++)
#pragma unroll
                for (int j = 0; j < 8; j++)
                    acc[i][j] += ar[i] * br[j];
        }
        __syncthreads();
    }

    // epilogue with bias
#pragma unroll
    for (int i = 0; i < 8; i++) {
        int row = m0 + tr * 8 + i;
#pragma unroll
        for (int j = 0; j < 8; j += 4) {
            int col = n0 + tc * 8 + j;
            float4 o;
            o.x = acc[i][j + 0] + bias[col + 0];
            o.y = acc[i][j + 1] + bias[col + 1];
            o.z = acc[i][j + 2] + bias[col + 2];
            o.w = acc[i][j + 3] + bias[col + 3];
            *(float4*)(C + (size_t)row * N + col) = o;
        }
    }
}

// ==================== Flash attention (causal), fp32 ====================
// Per block: one (b,h), 128 query rows. Bc=64 key tile. 256 threads.
// Thread (tr,tc): tr=tid/16 owns rows tr*8..+7; tc=tid%16 owns 4 score cols / 4 out dims.
// Q,K stored transposed [d][row] with XOR chunk-swizzle (4-float chunks) to avoid
// both transpose-store and fragment-read bank conflicts.
#define BR 128
#define BC 64

__global__ __launch_bounds__(256) void flash_attn(
    const float* __restrict__ Qg, const float* __restrict__ Kg,
    const float* __restrict__ Vg, float* __restrict__ Ctx)
{
    extern __shared__ float sm[];
    float* Qt = sm;                    // [64][128] swizzled  (32KB)
    float* Kt = Qt + 64 * 128;         // [64][64]  swizzled  (16KB)
    float* Vs = Kt + 64 * 64;          // [64][64]  natural   (16KB)
    float* Ps = Vs + 64 * 64;          // [128][64]           (32KB)

    const int tid = threadIdx.x;
    const int qt  = gridDim.x - 1 - blockIdx.x;   // big tiles launch first
    const int bh  = blockIdx.y;
    const int b   = bh >> 4;
    const int h   = bh & 15;
    const int i0  = qt * BR;
    const int tr  = tid >> 4;          // 0..15
    const int tc  = tid & 15;          // 0..15
    const float scale = 0.125f;        // 1/sqrt(64)

    // ---- load Q tile, transposed + swizzled ----
    for (int e = tid; e < BR * HDz; e += 256) {
        int r = e >> 6;                // 0..127
        int d = e & 63;
        float val = Qg[(size_t)(b * Sz + i0 + r) * Dz + h * HDz + d];
        int chunk = (r >> 2) ^ (d & 31);          // 0..31
        Qt[d * 128 + chunk * 4 + (r & 3)] = val;
    }

    float m_i[8], l_i[8], o[8][4];
#pragma unroll
    for (int i = 0; i < 8; i++) {
        m_i[i] = -1e30f; l_i[i] = 0.f;
#pragma unroll
        for (int j = 0; j < 4; j++) o[i][j] = 0.f;
    }
    __syncthreads();

    const int njt = (i0 + BR) / BC;    // kv tiles = 2*(qt+1)
    for (int jt = 0; jt < njt; jt++) {
        const int j0 = jt * BC;
        // ---- load K (transposed+swizzled) and V (natural) ----
        for (int e = tid; e < BC * HDz; e += 256) {
            int c = e >> 6;            // 0..63
            int d = e & 63;
            size_t gidx = (size_t)(b * Sz + j0 + c) * Dz + h * HDz + d;
            float kv = Kg[gidx];
            int chunk = (c >> 2) ^ (d & 15);      // 0..15
            Kt[d * 64 + chunk * 4 + (c & 3)] = kv;
            Vs[c * 64 + d] = Vg[gidx];
        }
        __syncthreads();

        // ---- scores S[8][4] = Q Kt ----
        float s[8][4];
#pragma unroll
        for (int i = 0; i < 8; i++)
#pragma unroll
            for (int j = 0; j < 4; j++) s[i][j] = 0.f;

#pragma unroll 8
        for (int k = 0; k < HDz; k++) {
            float qf[8], kf[4];
            int sw = k & 31;
            *(float4*)(qf)     = *(const float4*)(&Qt[k * 128 + (((2 * tr)     ^ sw) * 4)]);
            *(float4*)(qf + 4) = *(const float4*)(&Qt[k * 128 + (((2 * tr + 1) ^ sw) * 4)]);
            *(float4*)(kf)     = *(const float4*)(&Kt[k * 64  + ((tc ^ (k & 15)) * 4)]);
#pragma unroll
            for (int i = 0; i < 8; i++)
#pragma unroll
                for (int j = 0; j < 4; j++)
                    s[i][j] += qf[i] * kf[j];
        }

        // ---- scale + causal mask ----
#pragma unroll
        for (int i = 0; i < 8; i++) {
            int rg = i0 + tr * 8 + i;
#pragma unroll
            for (int j = 0; j < 4; j++) {
                int cg = j0 + tc * 4 + j;
                float v = s[i][j] * scale;
                s[i][j] = (cg > rg) ? -1e30f : v;
            }
        }

        // ---- online softmax (row groups = 16 consecutive lanes) ----
#pragma unroll
        for (int i = 0; i < 8; i++) {
            float mt = fmaxf(fmaxf(s[i][0], s[i][1]), fmaxf(s[i][2], s[i][3]));
#pragma unroll
            for (int w = 8; w >= 1; w >>= 1)
                mt = fmaxf(mt, __shfl_xor_sync(0xffffffffu, mt, w));
            float mn = fmaxf(m_i[i], mt);
            float alpha = __expf(m_i[i] - mn);
            m_i[i] = mn;
            float rs = 0.f;
#pragma unroll
            for (int j = 0; j < 4; j++) {
                s[i][j] = __expf(s[i][j] - mn);
                rs += s[i][j];
            }
#pragma unroll
            for (int w = 8; w >= 1; w >>= 1)
                rs += __shfl_xor_sync(0xffffffffu, rs, w);
            l_i[i] = l_i[i] * alpha + rs;
#pragma unroll
            for (int j = 0; j < 4; j++) o[i][j] *= alpha;
        }

        // ---- stage P to smem ----
#pragma unroll
        for (int i = 0; i < 8; i++)
            *(float4*)(&Ps[(tr * 8 + i) * 64 + tc * 4]) = *(const float4*)(&s[i][0]);
        __syncthreads();

        // ---- O += P @ V ----
#pragma unroll 4
        for (int cc = 0; cc < BC; cc += 4) {
            float p[8][4], vv[4][4];
#pragma unroll
            for (int i = 0; i < 8; i++)
                *(float4*)(p[i]) = *(const float4*)(&Ps[(tr * 8 + i) * 64 + cc]);
#pragma unroll
            for (int x = 0; x < 4; x++)
                *(float4*)(vv[x]) = *(const float4*)(&Vs[(cc + x) * 64 + tc * 4]);
#pragma unroll
            for (int i = 0; i < 8; i++)
#pragma unroll
                for (int x = 0; x < 4; x++)
#pragma unroll
                    for (int j = 0; j < 4; j++)
                        o[i][j] += p[i][x] * vv[x][j];
        }
        __syncthreads();   // before next tile overwrites Kt/Vs
    }

    // ---- normalize and write ctx (merged-head layout [B,S,D]) ----
#pragma unroll
    for (int i = 0; i < 8; i++) {
        float inv = 1.0f / l_i[i];
        float4 ov;
        ov.x = o[i][0] * inv; ov.y = o[i][1] * inv;
        ov.z = o[i][2] * inv; ov.w = o[i][3] * inv;
        *(float4*)(&Ctx[(size_t)(b * Sz + i0 + tr * 8 + i) * Dz + h * HDz + tc * 4]) = ov;
    }
}

// ==================== launch ====================
extern "C" void kernel_launch(void* const* d_in, const int* in_sizes, int n_in,
                              void* d_out, int out_size)
{
    const float* x  = (const float*)d_in[0];
    const float* Wq = (const float*)d_in[1];
    const float* bq = (const float*)d_in[2];
    const float* Wk = (const float*)d_in[3];
    const float* bk = (const float*)d_in[4];
    const float* Wv = (const float*)d_in[5];
    const float* bv = (const float*)d_in[6];
    const float* Wo = (const float*)d_in[7];
    const float* bo = (const float*)d_in[8];
    float* out = (float*)d_out;

    float *gq, *gk, *gv, *gctx;
    cudaGetSymbolAddress((void**)&gq,   g_q);
    cudaGetSymbolAddress((void**)&gk,   g_k);
    cudaGetSymbolAddress((void**)&gv,   g_v);
    cudaGetSymbolAddress((void**)&gctx, g_ctx);

    dim3 gg(Dz / 128, Mz / 128);   // (8, 32)
    sgemm_bias<<<gg, 256>>>(x, Wq, bq, gq, Mz, Dz, Dz);
    sgemm_bias<<<gg, 256>>>(x, Wk, bk, gk, Mz, Dz, Dz);
    sgemm_bias<<<gg, 256>>>(x, Wv, bv, gv, Mz, Dz, Dz);

    size_t smem = (size_t)(64 * 128 + 64 * 64 + 64 * 64 + 128 * 64) * sizeof(float); // 96KB
    cudaFuncSetAttribute(flash_attn, cudaFuncAttributeMaxDynamicSharedMemorySize, (int)smem);
    flash_attn<<<dim3(Sz / BR, Bz * Hz), 256, smem>>>(gq, gk, gv, gctx);

    sgemm_bias<<<gg, 256>>>(gctx, Wo, bo, out, Mz, Dz, Dz);
}

// round 3
// speedup vs baseline: 1.5062x; 1.5062x over previous
#include <cuda_runtime.h>
#include <cuda_bf16.h>
#include <cstdint>

// Problem constants
#define Bz 2
#define Sz 2048
#define Dz 1024
#define Hz 16
#define HDz 64
#define Mz (Bz*Sz)          // 4096 rows

// -------------------- scratch (device globals; no allocation) --------------------
__device__ float g_q[Mz * Dz];
__device__ float g_k[Mz * Dz];
__device__ float g_v[Mz * Dz];
__device__ float g_ctx[Mz * Dz];
__device__ __nv_bfloat16 g_ah[Mz * Dz];       // activation hi split
__device__ __nv_bfloat16 g_al[Mz * Dz];       // activation lo split
__device__ __nv_bfloat16 g_wth[4][Dz * Dz];   // W^T hi (q,k,v,o)
__device__ __nv_bfloat16 g_wtl[4][Dz * Dz];   // W^T lo

// ==================== helpers ====================
__device__ __forceinline__ uint32_t smem_u32(const void* p) {
    uint32_t a;
    asm("{ .reg .u64 t; cvta.to.shared.u64 t, %1; cvt.u32.u64 %0, t; }" : "=r"(a) : "l"(p));
    return a;
}

#define CP_ASYNC16(saddr, gptr) \
    asm volatile("cp.async.cg.shared.global [%0], [%1], 16;" :: "r"(saddr), "l"(gptr) : "memory")
#define CP_COMMIT() asm volatile("cp.async.commit_group;" ::: "memory")
#define CP_WAIT2()  asm volatile("cp.async.wait_group 2;" ::: "memory")

__device__ __forceinline__ void ldm_x4(uint32_t* r, uint32_t addr) {
    asm volatile("ldmatrix.sync.aligned.m8n8.x4.shared.b16 {%0,%1,%2,%3}, [%4];"
                 : "=r"(r[0]), "=r"(r[1]), "=r"(r[2]), "=r"(r[3]) : "r"(addr));
}
__device__ __forceinline__ void mma_16816(float* c, const uint32_t* a, const uint32_t* b) {
    asm volatile(
        "mma.sync.aligned.m16n8k16.row.col.f32.bf16.bf16.f32 "
        "{%0,%1,%2,%3}, {%4,%5,%6,%7}, {%8,%9}, {%0,%1,%2,%3};"
        : "+f"(c[0]), "+f"(c[1]), "+f"(c[2]), "+f"(c[3])
        : "r"(a[0]), "r"(a[1]), "r"(a[2]), "r"(a[3]), "r"(b[0]), "r"(b[1]));
}

// ==================== split fp32 -> bf16 hi/lo ====================
__global__ __launch_bounds__(256) void split_bf16(
    const float* __restrict__ in, __nv_bfloat16* __restrict__ hi,
    __nv_bfloat16* __restrict__ lo, int n)
{
    int i = (blockIdx.x * 256 + threadIdx.x) * 4;
    if (i >= n) return;
    float4 v = *(const float4*)(in + i);
    float f[4] = {v.x, v.y, v.z, v.w};
    __nv_bfloat16 h[4], l[4];
#pragma unroll
    for (int j = 0; j < 4; j++) {
        h[j] = __float2bfloat16(f[j]);
        l[j] = __float2bfloat16(f[j] - __bfloat162float(h[j]));
    }
    __nv_bfloat162 h01, h23, l01, l23;
    h01.x = h[0]; h01.y = h[1]; h23.x = h[2]; h23.y = h[3];
    l01.x = l[0]; l01.y = l[1]; l23.x = l[2]; l23.y = l[3];
    ((__nv_bfloat162*)(hi + i))[0] = h01;
    ((__nv_bfloat162*)(hi + i))[1] = h23;
    ((__nv_bfloat162*)(lo + i))[0] = l01;
    ((__nv_bfloat162*)(lo + i))[1] = l23;
}

// ==================== transpose + split: W[K,N] -> Wt[N,K] bf16 hi/lo ====================
__global__ __launch_bounds__(256) void transpose_split(
    const float* __restrict__ W, __nv_bfloat16* __restrict__ Th,
    __nv_bfloat16* __restrict__ Tl)
{
    __shared__ float t[32][33];
    int n0 = blockIdx.x * 32, k0 = blockIdx.y * 32;
    int tx = threadIdx.x, ty = threadIdx.y;
#pragma unroll
    for (int i = ty; i < 32; i += 8)
        t[i][tx] = W[(size_t)(k0 + i) * Dz + n0 + tx];
    __syncthreads();
#pragma unroll
    for (int i = ty; i < 32; i += 8) {
        float v = t[tx][i];                 // = W[k0+tx][n0+i]
        __nv_bfloat16 h = __float2bfloat16(v);
        __nv_bfloat16 l = __float2bfloat16(v - __bfloat162float(h));
        Th[(size_t)(n0 + i) * Dz + k0 + tx] = h;
        Tl[(size_t)(n0 + i) * Dz + k0 + tx] = l;
    }
}

// ==================== HMMA bf16x3 GEMM: C[M,N] = A@W + bias ====================
// A splits [M,K] bf16 row-major; B splits = W^T [N,K] bf16 row-major.
// CTA tile 128x128, warp tile 64x32 (warps 2x4), K-chunk 64, 3-stage cp.async.
// Smem per stage: Ah|Al|Bh|Bl, each 128 rows x 128B (64 bf16), XOR-16B-chunk swizzle.
#define NKC (Dz / 64)         // 16
#define STAGE_BYTES 65536     // 4 * 16KB

__global__ __launch_bounds__(256) void gemm_hmma_x3(
    const __nv_bfloat16* __restrict__ Ah, const __nv_bfloat16* __restrict__ Al,
    const __nv_bfloat16* __restrict__ Bh, const __nv_bfloat16* __restrict__ Bl,
    const float* __restrict__ bias, float* __restrict__ C)
{
    extern __shared__ char dsm[];
    const int tid = threadIdx.x;
    const int wid = tid >> 5;
    const int lane = tid & 31;
    const int lq = lane >> 3;          // 0..3 (ldmatrix mat index)
    const int lr = lane & 7;
    const int wm = wid & 1;            // warp M index (0..1), 64 rows each
    const int wn = wid >> 1;           // warp N index (0..3), 32 cols each
    const int m0 = blockIdx.y * 128;
    const int n0 = blockIdx.x * 128;

    uint32_t dynu = smem_u32(dsm);
    uint32_t base = (dynu + 1023) & ~1023u;   // 1KB-align tile area

    const __nv_bfloat16* srcs[4] = {Ah, Al, Bh, Bl};
    const int row0s[4] = {m0, m0, n0, n0};

    // ---- stage loader: 4 tiles of 128 rows x 64 bf16 each, 16B-chunk swizzled ----
    auto load_stage = [&](int buf, int kc) {
        uint32_t sb = base + buf * STAGE_BYTES;
#pragma unroll
        for (int t = 0; t < 4; t++) {
            const __nv_bfloat16* src = srcs[t] + (size_t)row0s[t] * Dz + kc * 64;
            uint32_t dst = sb + t * 16384;
#pragma unroll
            for (int it = 0; it < 4; it++) {
                int idx = tid + it * 256;       // 0..1023
                int r = idx >> 3;               // 0..127
                int c = idx & 7;                // 16B chunk
                CP_ASYNC16(dst + r * 128 + ((c ^ (r & 7)) << 4),
                           src + (size_t)r * Dz + c * 8);
            }
        }
    };

    float acc[4][4][4];
#pragma unroll
    for (int i = 0; i < 4; i++)
#pragma unroll
        for (int j = 0; j < 4; j++)
#pragma unroll
            for (int k = 0; k < 4; k++) acc[i][j][k] = 0.f;

    // prologue: fill 3 stages
    load_stage(0, 0); CP_COMMIT();
    load_stage(1, 1); CP_COMMIT();
    load_stage(2, 2); CP_COMMIT();

    // per-thread fragment address components
    const int rowA = wm * 64 + lr + (lq & 1) * 8;     // + mi*16
    const int chA  = (lq >> 1);                        // + 2*ks
    const int rowB = wn * 32 + lr + (lq >> 1) * 8;     // + nb (0/16)
    const int chB  = (lq & 1);                         // + 2*ks

    for (int kc = 0; kc < NKC; kc++) {
        CP_WAIT2();
        __syncthreads();
        uint32_t sb = base + (kc % 3) * STAGE_BYTES;
        uint32_t sAh = sb, sAl = sb + 16384, sBh = sb + 32768, sBl = sb + 49152;

#pragma unroll
        for (int ks = 0; ks < 4; ks++) {
            // B fragments: 4 n8-tiles per split; one x4 covers two tiles
            uint32_t bh[8], bl[8];
#pragma unroll
            for (int nb = 0; nb < 2; nb++) {
                uint32_t off = (uint32_t)(rowB + nb * 16) * 128 +
                               (uint32_t)(((2 * ks + chB) ^ lr) << 4);
                ldm_x4(&bh[nb * 4], sBh + off);
                ldm_x4(&bl[nb * 4], sBl + off);
            }
#pragma unroll
            for (int mi = 0; mi < 4; mi++) {
                uint32_t off = (uint32_t)(rowA + mi * 16) * 128 +
                               (uint32_t)(((2 * ks + chA) ^ lr) << 4);
                uint32_t ah[4], al[4];
                ldm_x4(ah, sAh + off);
                ldm_x4(al, sAl + off);
#pragma unroll
                for (int ni = 0; ni < 4; ni++) {
                    mma_16816(acc[mi][ni], ah, &bh[ni * 2]);
                    mma_16816(acc[mi][ni], ah, &bl[ni * 2]);
                    mma_16816(acc[mi][ni], al, &bh[ni * 2]);
                }
            }
        }
        __syncthreads();
        if (kc + 3 < NKC) load_stage(kc % 3, kc + 3);
        CP_COMMIT();
    }

    // ---- epilogue: direct stores with bias ----
    const int rbase = m0 + wm * 64 + (lane >> 2);
    const int cbase = n0 + wn * 32 + (lane & 3) * 2;
#pragma unroll
    for (int mi = 0; mi < 4; mi++) {
#pragma unroll
        for (int ni = 0; ni < 4; ni++) {
            int col = cbase + ni * 8;
            float b0 = bias[col], b1 = bias[col + 1];
            int r0 = rbase + mi * 16;
            float2 v0 = {acc[mi][ni][0] + b0, acc[mi][ni][1] + b1};
            float2 v1 = {acc[mi][ni][2] + b0, acc[mi][ni][3] + b1};
            *(float2*)(C + (size_t)r0 * Dz + col) = v0;
            *(float2*)(C + (size_t)(r0 + 8) * Dz + col) = v1;
        }
    }
}

// ==================== Flash attention (causal), fp32 (proven R1 kernel) ====================
#define BR 128
#define BC 64

__global__ __launch_bounds__(256) void flash_attn(
    const float* __restrict__ Qg, const float* __restrict__ Kg,
    const float* __restrict__ Vg, float* __restrict__ Ctx)
{
    extern __shared__ float sm[];
    float* Qt = sm;
    float* Kt = Qt + 64 * 128;
    float* Vs = Kt + 64 * 64;
    float* Ps = Vs + 64 * 64;

    const int tid = threadIdx.x;
    const int qt  = gridDim.x - 1 - blockIdx.x;
    const int bh  = blockIdx.y;
    const int b   = bh >> 4;
    const int h   = bh & 15;
    const int i0  = qt * BR;
    const int tr  = tid >> 4;
    const int tc  = tid & 15;
    const float scale = 0.125f;

    for (int e = tid; e < BR * HDz; e += 256) {
        int r = e >> 6;
        int d = e & 63;
        float val = Qg[(size_t)(b * Sz + i0 + r) * Dz + h * HDz + d];
        int chunk = (r >> 2) ^ (d & 31);
        Qt[d * 128 + chunk * 4 + (r & 3)] = val;
    }

    float m_i[8], l_i[8], o[8][4];
#pragma unroll
    for (int i = 0; i < 8; i++) {
        m_i[i] = -1e30f; l_i[i] = 0.f;
#pragma unroll
        for (int j = 0; j < 4; j++) o[i][j] = 0.f;
    }
    __syncthreads();

    const int njt = (i0 + BR) / BC;
    for (int jt = 0; jt < njt; jt++) {
        const int j0 = jt * BC;
        for (int e = tid; e < BC * HDz; e += 256) {
            int c = e >> 6;
            int d = e & 63;
            size_t gidx = (size_t)(b * Sz + j0 + c) * Dz + h * HDz + d;
            float kv = Kg[gidx];
            int chunk = (c >> 2) ^ (d & 15);
            Kt[d * 64 + chunk * 4 + (c & 3)] = kv;
            Vs[c * 64 + d] = Vg[gidx];
        }
        __syncthreads();

        float s[8][4];
#pragma unroll
        for (int i = 0; i < 8; i++)
#pragma unroll
            for (int j = 0; j < 4; j++) s[i][j] = 0.f;

#pragma unroll 8
        for (int k = 0; k < HDz; k++) {
            float qf[8], kf[4];
            int sw = k & 31;
            *(float4*)(qf)     = *(const float4*)(&Qt[k * 128 + (((2 * tr)     ^ sw) * 4)]);
            *(float4*)(qf + 4) = *(const float4*)(&Qt[k * 128 + (((2 * tr + 1) ^ sw) * 4)]);
            *(float4*)(kf)     = *(const float4*)(&Kt[k * 64  + ((tc ^ (k & 15)) * 4)]);
#pragma unroll
            for (int i = 0; i < 8; i++)
#pragma unroll
                for (int j = 0; j < 4; j++)
                    s[i][j] += qf[i] * kf[j];
        }

#pragma unroll
        for (int i = 0; i < 8; i++) {
            int rg = i0 + tr * 8 + i;
#pragma unroll
            for (int j = 0; j < 4; j++) {
                int cg = j0 + tc * 4 + j;
                float v = s[i][j] * scale;
                s[i][j] = (cg > rg) ? -1e30f : v;
            }
        }

#pragma unroll
        for (int i = 0; i < 8; i++) {
            float mt = fmaxf(fmaxf(s[i][0], s[i][1]), fmaxf(s[i][2], s[i][3]));
#pragma unroll
            for (int w = 8; w >= 1; w >>= 1)
                mt = fmaxf(mt, __shfl_xor_sync(0xffffffffu, mt, w));
            float mn = fmaxf(m_i[i], mt);
            float alpha = __expf(m_i[i] - mn);
            m_i[i] = mn;
            float rs = 0.f;
#pragma unroll
            for (int j = 0; j < 4; j++) {
                s[i][j] = __expf(s[i][j] - mn);
                rs += s[i][j];
            }
#pragma unroll
            for (int w = 8; w >= 1; w >>= 1)
                rs += __shfl_xor_sync(0xffffffffu, rs, w);
            l_i[i] = l_i[i] * alpha + rs;
#pragma unroll
            for (int j = 0; j < 4; j++) o[i][j] *= alpha;
        }

#pragma unroll
        for (int i = 0; i < 8; i++)
            *(float4*)(&Ps[(tr * 8 + i) * 64 + tc * 4]) = *(const float4*)(&s[i][0]);
        __syncthreads();

#pragma unroll 4
        for (int cc = 0; cc < BC; cc += 4) {
            float p[8][4], vv[4][4];
#pragma unroll
            for (int i = 0; i < 8; i++)
                *(float4*)(p[i]) = *(const float4*)(&Ps[(tr * 8 + i) * 64 + cc]);
#pragma unroll
            for (int x = 0; x < 4; x++)
                *(float4*)(vv[x]) = *(const float4*)(&Vs[(cc + x) * 64 + tc * 4]);
#pragma unroll
            for (int i = 0; i < 8; i++)
#pragma unroll
                for (int x = 0; x < 4; x++)
#pragma unroll
                    for (int j = 0; j < 4; j++)
                        o[i][j] += p[i][x] * vv[x][j];
        }
        __syncthreads();
    }

#pragma unroll
    for (int i = 0; i < 8; i++) {
        float inv = 1.0f / l_i[i];
        float4 ov;
        ov.x = o[i][0] * inv; ov.y = o[i][1] * inv;
        ov.z = o[i][2] * inv; ov.w = o[i][3] * inv;
        *(float4*)(&Ctx[(size_t)(b * Sz + i0 + tr * 8 + i) * Dz + h * HDz + tc * 4]) = ov;
    }
}

// ==================== launch ====================
extern "C" void kernel_launch(void* const* d_in, const int* in_sizes, int n_in,
                              void* d_out, int out_size)
{
    const float* x  = (const float*)d_in[0];
    const float* Wq = (const float*)d_in[1];
    const float* bq = (const float*)d_in[2];
    const float* Wk = (const float*)d_in[3];
    const float* bk = (const float*)d_in[4];
    const float* Wv = (const float*)d_in[5];
    const float* bv = (const float*)d_in[6];
    const float* Wo = (const float*)d_in[7];
    const float* bo = (const float*)d_in[8];
    float* out = (float*)d_out;

    float *gq, *gk, *gv, *gctx;
    __nv_bfloat16 *gah, *gal, *gwth, *gwtl;
    cudaGetSymbolAddress((void**)&gq,   g_q);
    cudaGetSymbolAddress((void**)&gk,   g_k);
    cudaGetSymbolAddress((void**)&gv,   g_v);
    cudaGetSymbolAddress((void**)&gctx, g_ctx);
    cudaGetSymbolAddress((void**)&gah,  g_ah);
    cudaGetSymbolAddress((void**)&gal,  g_al);
    cudaGetSymbolAddress((void**)&gwth, g_wth);
    cudaGetSymbolAddress((void**)&gwtl, g_wtl);

    const int WSZ = Dz * Dz;
    __nv_bfloat16* wth[4] = {gwth, gwth + WSZ, gwth + 2 * WSZ, gwth + 3 * WSZ};
    __nv_bfloat16* wtl[4] = {gwtl, gwtl + WSZ, gwtl + 2 * WSZ, gwtl + 3 * WSZ};
    const float* Ws[4] = {Wq, Wk, Wv, Wo};

    // split activations
    split_bf16<<<Mz * Dz / 1024, 256>>>(x, gah, gal, Mz * Dz);
    // transpose + split weights
    for (int i = 0; i < 4; i++)
        transpose_split<<<dim3(32, 32), dim3(32, 8)>>>(Ws[i], wth[i], wtl[i]);

    // tensor-core (HMMA) projection GEMMs
    size_t gsm = 3 * STAGE_BYTES + 1024;   // 197632
    cudaFuncSetAttribute(gemm_hmma_x3, cudaFuncAttributeMaxDynamicSharedMemorySize, (int)gsm);
    dim3 gg(Dz / 128, Mz / 128);   // (8, 32)
    gemm_hmma_x3<<<gg, 256, gsm>>>(gah, gal, wth[0], wtl[0], bq, gq);
    gemm_hmma_x3<<<gg, 256, gsm>>>(gah, gal, wth[1], wtl[1], bk, gk);
    gemm_hmma_x3<<<gg, 256, gsm>>>(gah, gal, wth[2], wtl[2], bv, gv);

    // attention (fp32)
    size_t smem = (size_t)(64 * 128 + 64 * 64 + 64 * 64 + 128 * 64) * sizeof(float);
    cudaFuncSetAttribute(flash_attn, cudaFuncAttributeMaxDynamicSharedMemorySize, (int)smem);
    flash_attn<<<dim3(Sz / BR, Bz * Hz), 256, smem>>>(gq, gk, gv, gctx);

    // output projection
    split_bf16<<<Mz * Dz / 1024, 256>>>(gctx, gah, gal, Mz * Dz);
    gemm_hmma_x3<<<gg, 256, gsm>>>(gah, gal, wth[3], wtl[3], bo, out);
}

// round 4
// speedup vs baseline: 3.0486x; 2.0241x over previous
#include <cuda_runtime.h>
#include <cuda_bf16.h>
#include <cstdint>

// Problem constants
#define Bz 2
#define Sz 2048
#define Dz 1024
#define Hz 16
#define HDz 64
#define Mz (Bz*Sz)          // 4096 rows

// -------------------- scratch (device globals; no allocation) --------------------
__device__ __nv_bfloat16 g_qh[Mz * Dz];
__device__ __nv_bfloat16 g_ql[Mz * Dz];
__device__ __nv_bfloat16 g_kh[Mz * Dz];
__device__ __nv_bfloat16 g_kl[Mz * Dz];
__device__ __nv_bfloat16 g_vth[Mz * Dz];      // V^T per head: [bh][d][s]
__device__ __nv_bfloat16 g_vtl[Mz * Dz];
__device__ __nv_bfloat16 g_cth[Mz * Dz];      // ctx hi/lo
__device__ __nv_bfloat16 g_ctl[Mz * Dz];
__device__ __nv_bfloat16 g_ah[Mz * Dz];       // x splits
__device__ __nv_bfloat16 g_al[Mz * Dz];
__device__ __nv_bfloat16 g_wth[4][Dz * Dz];   // W^T hi (q,k,v,o)
__device__ __nv_bfloat16 g_wtl[4][Dz * Dz];   // W^T lo

// ==================== helpers ====================
__device__ __forceinline__ uint32_t smem_u32(const void* p) {
    uint32_t a;
    asm("{ .reg .u64 t; cvta.to.shared.u64 t, %1; cvt.u32.u64 %0, t; }" : "=r"(a) : "l"(p));
    return a;
}
#define CP_ASYNC16(saddr, gptr) \
    asm volatile("cp.async.cg.shared.global [%0], [%1], 16;" :: "r"(saddr), "l"(gptr) : "memory")
#define CP_COMMIT() asm volatile("cp.async.commit_group;" ::: "memory")
#define CP_WAIT(n)  asm volatile("cp.async.wait_group %0;" :: "n"(n) : "memory")

__device__ __forceinline__ void ldm_x4(uint32_t* r, uint32_t addr) {
    asm volatile("ldmatrix.sync.aligned.m8n8.x4.shared.b16 {%0,%1,%2,%3}, [%4];"
                 : "=r"(r[0]), "=r"(r[1]), "=r"(r[2]), "=r"(r[3]) : "r"(addr));
}
__device__ __forceinline__ void mma_16816(float* c, const uint32_t* a, const uint32_t* b) {
    asm volatile(
        "mma.sync.aligned.m16n8k16.row.col.f32.bf16.bf16.f32 "
        "{%0,%1,%2,%3}, {%4,%5,%6,%7}, {%8,%9}, {%0,%1,%2,%3};"
        : "+f"(c[0]), "+f"(c[1]), "+f"(c[2]), "+f"(c[3])
        : "r"(a[0]), "r"(a[1]), "r"(a[2]), "r"(a[3]), "r"(b[0]), "r"(b[1]));
}
// split two floats into packed bf16x2 hi and lo residual
__device__ __forceinline__ void split2(float f0, float f1, uint32_t& hi, uint32_t& lo) {
    __nv_bfloat162 h, l;
    h.x = __float2bfloat16(f0);
    h.y = __float2bfloat16(f1);
    l.x = __float2bfloat16(f0 - __bfloat162float(h.x));
    l.y = __float2bfloat16(f1 - __bfloat162float(h.y));
    hi = *(uint32_t*)&h;
    lo = *(uint32_t*)&l;
}

// ==================== split fp32 -> bf16 hi/lo ====================
__global__ __launch_bounds__(256) void split_bf16(
    const float* __restrict__ in, __nv_bfloat16* __restrict__ hi,
    __nv_bfloat16* __restrict__ lo, int n)
{
    int i = (blockIdx.x * 256 + threadIdx.x) * 4;
    if (i >= n) return;
    float4 v = *(const float4*)(in + i);
    float f[4] = {v.x, v.y, v.z, v.w};
    uint32_t h01, l01, h23, l23;
    split2(f[0], f[1], h01, l01);
    split2(f[2], f[3], h23, l23);
    ((uint32_t*)(hi + i))[0] = h01;
    ((uint32_t*)(hi + i))[1] = h23;
    ((uint32_t*)(lo + i))[0] = l01;
    ((uint32_t*)(lo + i))[1] = l23;
}

// ==================== transpose + split: W[K,N] -> Wt[N,K] bf16 hi/lo ====================
__global__ __launch_bounds__(256) void transpose_split(
    const float* __restrict__ W, __nv_bfloat16* __restrict__ Th,
    __nv_bfloat16* __restrict__ Tl)
{
    __shared__ float t[32][33];
    int n0 = blockIdx.x * 32, k0 = blockIdx.y * 32;
    int tx = threadIdx.x, ty = threadIdx.y;
#pragma unroll
    for (int i = ty; i < 32; i += 8)
        t[i][tx] = W[(size_t)(k0 + i) * Dz + n0 + tx];
    __syncthreads();
#pragma unroll
    for (int i = ty; i < 32; i += 8) {
        float v = t[tx][i];
        __nv_bfloat16 h = __float2bfloat16(v);
        __nv_bfloat16 l = __float2bfloat16(v - __bfloat162float(h));
        Th[(size_t)(n0 + i) * Dz + k0 + tx] = h;
        Tl[(size_t)(n0 + i) * Dz + k0 + tx] = l;
    }
}

// ==================== HMMA bf16x3 GEMM ====================
// MODE 0: fp32 C = acc + bias
// MODE 1: bf16 hi/lo split of (acc+bias)*scale, row-major [M][1024]
// MODE 2: bf16 hi/lo split, transposed per-head: vt[bh][d][s]
#define NKC (Dz / 64)         // 16
#define STAGE_BYTES 65536     // 4 * 16KB

template<int MODE>
__global__ __launch_bounds__(256) void gemm_hmma_x3(
    const __nv_bfloat16* __restrict__ Ah, const __nv_bfloat16* __restrict__ Al,
    const __nv_bfloat16* __restrict__ Bh, const __nv_bfloat16* __restrict__ Bl,
    const float* __restrict__ bias, float* __restrict__ C,
    __nv_bfloat16* __restrict__ OH, __nv_bfloat16* __restrict__ OL, float scale)
{
    extern __shared__ char dsm[];
    const int tid = threadIdx.x;
    const int wid = tid >> 5;
    const int lane = tid & 31;
    const int lq = lane >> 3;
    const int lr = lane & 7;
    const int wm = wid & 1;
    const int wn = wid >> 1;
    const int m0 = blockIdx.y * 128;
    const int n0 = blockIdx.x * 128;

    uint32_t dynu = smem_u32(dsm);
    uint32_t base = (dynu + 1023) & ~1023u;

    const __nv_bfloat16* srcs[4] = {Ah, Al, Bh, Bl};
    const int row0s[4] = {m0, m0, n0, n0};

    auto load_stage = [&](int buf, int kc) {
        uint32_t sb = base + buf * STAGE_BYTES;
#pragma unroll
        for (int t = 0; t < 4; t++) {
            const __nv_bfloat16* src = srcs[t] + (size_t)row0s[t] * Dz + kc * 64;
            uint32_t dst = sb + t * 16384;
#pragma unroll
            for (int it = 0; it < 4; it++) {
                int idx = tid + it * 256;
                int r = idx >> 3;
                int c = idx & 7;
                CP_ASYNC16(dst + r * 128 + ((c ^ (r & 7)) << 4),
                           src + (size_t)r * Dz + c * 8);
            }
        }
    };

    float acc[4][4][4];
#pragma unroll
    for (int i = 0; i < 4; i++)
#pragma unroll
        for (int j = 0; j < 4; j++)
#pragma unroll
            for (int k = 0; k < 4; k++) acc[i][j][k] = 0.f;

    load_stage(0, 0); CP_COMMIT();
    load_stage(1, 1); CP_COMMIT();
    load_stage(2, 2); CP_COMMIT();

    const int rowA = wm * 64 + lr + (lq & 1) * 8;
    const int chA  = (lq >> 1);
    const int rowB = wn * 32 + lr + (lq >> 1) * 8;
    const int chB  = (lq & 1);

    for (int kc = 0; kc < NKC; kc++) {
        CP_WAIT(2);
        __syncthreads();
        uint32_t sb = base + (kc % 3) * STAGE_BYTES;
        uint32_t sAh = sb, sAl = sb + 16384, sBh = sb + 32768, sBl = sb + 49152;

#pragma unroll
        for (int ks = 0; ks < 4; ks++) {
            uint32_t bh[8], bl[8];
#pragma unroll
            for (int nb = 0; nb < 2; nb++) {
                uint32_t off = (uint32_t)(rowB + nb * 16) * 128 +
                               (uint32_t)(((2 * ks + chB) ^ lr) << 4);
                ldm_x4(&bh[nb * 4], sBh + off);
                ldm_x4(&bl[nb * 4], sBl + off);
            }
#pragma unroll
            for (int mi = 0; mi < 4; mi++) {
                uint32_t off = (uint32_t)(rowA + mi * 16) * 128 +
                               (uint32_t)(((2 * ks + chA) ^ lr) << 4);
                uint32_t ah[4], al[4];
                ldm_x4(ah, sAh + off);
                ldm_x4(al, sAl + off);
#pragma unroll
                for (int ni = 0; ni < 4; ni++) {
                    mma_16816(acc[mi][ni], ah, &bh[ni * 2]);
                    mma_16816(acc[mi][ni], ah, &bl[ni * 2]);
                    mma_16816(acc[mi][ni], al, &bh[ni * 2]);
                }
            }
        }
        __syncthreads();
        if (kc + 3 < NKC) load_stage(kc % 3, kc + 3);
        CP_COMMIT();
    }

    const int rbase = m0 + wm * 64 + (lane >> 2);
    const int cbase = n0 + wn * 32 + (lane & 3) * 2;
#pragma unroll
    for (int mi = 0; mi < 4; mi++) {
#pragma unroll
        for (int ni = 0; ni < 4; ni++) {
            int col = cbase + ni * 8;
            float b0 = bias[col], b1 = bias[col + 1];
            int r0 = rbase + mi * 16;
            float v00 = acc[mi][ni][0] + b0, v01 = acc[mi][ni][1] + b1;
            float v10 = acc[mi][ni][2] + b0, v11 = acc[mi][ni][3] + b1;
            if (MODE == 0) {
                float2 a = {v00, v01}, b = {v10, v11};
                *(float2*)(C + (size_t)r0 * Dz + col) = a;
                *(float2*)(C + (size_t)(r0 + 8) * Dz + col) = b;
            } else if (MODE == 1) {
                uint32_t h0, l0, h1, l1;
                split2(v00 * scale, v01 * scale, h0, l0);
                split2(v10 * scale, v11 * scale, h1, l1);
                *(uint32_t*)(OH + (size_t)r0 * Dz + col) = h0;
                *(uint32_t*)(OL + (size_t)r0 * Dz + col) = l0;
                *(uint32_t*)(OH + (size_t)(r0 + 8) * Dz + col) = h1;
                *(uint32_t*)(OL + (size_t)(r0 + 8) * Dz + col) = l1;
            } else {
                // vt[((b*16+h)*64 + d)*2048 + s]
                float vs[4] = {v00, v01, v10, v11};
#pragma unroll
                for (int e = 0; e < 4; e++) {
                    int r = r0 + (e >> 1) * 8;
                    int c = col + (e & 1);
                    int bb = r >> 11, s = r & 2047;
                    int hh = c >> 6, d = c & 63;
                    size_t idx = ((size_t)((bb << 4) | hh) * 64 + d) * 2048 + s;
                    __nv_bfloat16 h = __float2bfloat16(vs[e]);
                    OH[idx] = h;
                    OL[idx] = __float2bfloat16(vs[e] - __bfloat162float(h));
                }
            }
        }
    }
}

// ==================== HMMA flash attention (causal), bf16x3 ====================
// Grid (16, 32): blockIdx.x -> q tile (reversed), blockIdx.y -> (b,h).
// 256 threads = 8 warps; warp w owns query rows [16w, 16w+16).
// Q pre-scaled by 1/8 in GEMM epilogue.
#define ABR 128
#define ABC 64

__global__ __launch_bounds__(256) void flash_hmma(
    const __nv_bfloat16* __restrict__ qh, const __nv_bfloat16* __restrict__ ql,
    const __nv_bfloat16* __restrict__ kh, const __nv_bfloat16* __restrict__ kl,
    const __nv_bfloat16* __restrict__ vth, const __nv_bfloat16* __restrict__ vtl,
    __nv_bfloat16* __restrict__ ch, __nv_bfloat16* __restrict__ cl)
{
    extern __shared__ char dsm[];
    const int tid = threadIdx.x;
    const int wid = tid >> 5;
    const int lane = tid & 31;
    const int lq = lane >> 3;
    const int lr = lane & 7;
    const int qt = gridDim.x - 1 - blockIdx.x;
    const int bh = blockIdx.y;
    const int b = bh >> 4;
    const int h = bh & 15;
    const int i0 = qt * ABR;

    uint32_t dynu = smem_u32(dsm);
    uint32_t base = (dynu + 1023) & ~1023u;
    uint32_t qb = base;                    // Qh 16KB, Ql 16KB
    uint32_t stg = base + 32768;           // 2 stages x 32KB: Kh|Kl|Vth|Vtl 8KB each

    // ---- load Q tile (128 rows x 64 bf16, hi+lo) ----
    {
        const __nv_bfloat16* qsrc[2] = {qh, ql};
#pragma unroll
        for (int it = 0; it < 8; it++) {
            int idx = tid + it * 256;          // 0..2047
            int t = idx >> 10;
            int rem = idx & 1023;
            int r = rem >> 3, c = rem & 7;
            CP_ASYNC16(qb + t * 16384 + r * 128 + ((c ^ (r & 7)) << 4),
                       qsrc[t] + (size_t)(b * Sz + i0 + r) * Dz + h * 64 + c * 8);
        }
    }

    auto load_stage = [&](int buf, int jt) {
        int j0 = jt * ABC;
        uint32_t sb = stg + buf * 32768;
#pragma unroll
        for (int it = 0; it < 8; it++) {
            int idx = tid + it * 256;          // 0..2047
            int arr = idx >> 9;
            int rem = idx & 511;
            int r = rem >> 3, c = rem & 7;
            const __nv_bfloat16* src;
            if (arr == 0)      src = kh  + (size_t)(b * Sz + j0 + r) * Dz + h * 64 + c * 8;
            else if (arr == 1) src = kl  + (size_t)(b * Sz + j0 + r) * Dz + h * 64 + c * 8;
            else if (arr == 2) src = vth + ((size_t)bh * 64 + r) * 2048 + j0 + c * 8;
            else               src = vtl + ((size_t)bh * 64 + r) * 2048 + j0 + c * 8;
            CP_ASYNC16(sb + arr * 8192 + r * 128 + ((c ^ (r & 7)) << 4), src);
        }
    };

    const int njt = (i0 + ABR) / ABC;
    load_stage(0, 0);
    CP_COMMIT();

    // fragment address components
    const int rowA = wid * 16 + lr + (lq & 1) * 8;   // Q / P rows
    const int chA  = lq >> 1;
    const int rowBb = lr + (lq >> 1) * 8;            // + nb*16
    const int chB  = lq & 1;

    // softmax state (rows r0 = lane>>2, r1 = r0+8 within warp band)
    float m0 = -1e30f, m1 = -1e30f, l0 = 0.f, l1 = 0.f;
    float o[8][4];
#pragma unroll
    for (int i = 0; i < 8; i++)
#pragma unroll
        for (int j = 0; j < 4; j++) o[i][j] = 0.f;

    for (int jt = 0; jt < njt; jt++) {
        if (jt + 1 < njt) { load_stage((jt + 1) & 1, jt + 1); CP_COMMIT(); CP_WAIT(1); }
        else CP_WAIT(0);
        __syncthreads();

        uint32_t sb = stg + (jt & 1) * 32768;
        uint32_t sKh = sb, sKl = sb + 8192, sVh = sb + 16384, sVl = sb + 24576;

        // ---- scores = Q K^T (x3 split) ----
        float sc[8][4];
#pragma unroll
        for (int i = 0; i < 8; i++)
#pragma unroll
            for (int j = 0; j < 4; j++) sc[i][j] = 0.f;

#pragma unroll
        for (int ks = 0; ks < 4; ks++) {
            uint32_t offA = (uint32_t)rowA * 128 + (uint32_t)(((2 * ks + chA) ^ lr) << 4);
            uint32_t ah[4], al[4];
            ldm_x4(ah, qb + offA);
            ldm_x4(al, qb + 16384 + offA);
            uint32_t kb[16];
#pragma unroll
            for (int nb = 0; nb < 4; nb++) {
                uint32_t off = (uint32_t)(nb * 16 + rowBb) * 128 +
                               (uint32_t)(((2 * ks + chB) ^ lr) << 4);
                ldm_x4(&kb[nb * 4], sKh + off);
            }
#pragma unroll
            for (int nt = 0; nt < 8; nt++) {
                mma_16816(sc[nt], ah, &kb[nt * 2]);
                mma_16816(sc[nt], al, &kb[nt * 2]);
            }
#pragma unroll
            for (int nb = 0; nb < 4; nb++) {
                uint32_t off = (uint32_t)(nb * 16 + rowBb) * 128 +
                               (uint32_t)(((2 * ks + chB) ^ lr) << 4);
                ldm_x4(&kb[nb * 4], sKl + off);
            }
#pragma unroll
            for (int nt = 0; nt < 8; nt++)
                mma_16816(sc[nt], ah, &kb[nt * 2]);
        }

        // ---- causal mask (diagonal tiles only) ----
        int j0 = jt * ABC;
        int rg0 = i0 + wid * 16 + (lane >> 2);
        if (j0 + ABC - 1 > i0) {
#pragma unroll
            for (int nt = 0; nt < 8; nt++) {
                int cg = j0 + nt * 8 + (lane & 3) * 2;
                if (cg > rg0)     sc[nt][0] = -1e30f;
                if (cg + 1 > rg0) sc[nt][1] = -1e30f;
                if (cg > rg0 + 8)     sc[nt][2] = -1e30f;
                if (cg + 1 > rg0 + 8) sc[nt][3] = -1e30f;
            }
        }

        // ---- online softmax ----
        float mx0 = -1e30f, mx1 = -1e30f;
#pragma unroll
        for (int nt = 0; nt < 8; nt++) {
            mx0 = fmaxf(mx0, fmaxf(sc[nt][0], sc[nt][1]));
            mx1 = fmaxf(mx1, fmaxf(sc[nt][2], sc[nt][3]));
        }
        mx0 = fmaxf(mx0, __shfl_xor_sync(0xffffffffu, mx0, 1));
        mx0 = fmaxf(mx0, __shfl_xor_sync(0xffffffffu, mx0, 2));
        mx1 = fmaxf(mx1, __shfl_xor_sync(0xffffffffu, mx1, 1));
        mx1 = fmaxf(mx1, __shfl_xor_sync(0xffffffffu, mx1, 2));
        float mn0 = fmaxf(m0, mx0), mn1 = fmaxf(m1, mx1);
        float a0 = __expf(m0 - mn0), a1 = __expf(m1 - mn1);
        m0 = mn0; m1 = mn1;
        float rs0 = 0.f, rs1 = 0.f;
#pragma unroll
        for (int nt = 0; nt < 8; nt++) {
            sc[nt][0] = __expf(sc[nt][0] - mn0);
            sc[nt][1] = __expf(sc[nt][1] - mn0);
            sc[nt][2] = __expf(sc[nt][2] - mn1);
            sc[nt][3] = __expf(sc[nt][3] - mn1);
            rs0 += sc[nt][0] + sc[nt][1];
            rs1 += sc[nt][2] + sc[nt][3];
        }
        rs0 += __shfl_xor_sync(0xffffffffu, rs0, 1);
        rs0 += __shfl_xor_sync(0xffffffffu, rs0, 2);
        rs1 += __shfl_xor_sync(0xffffffffu, rs1, 1);
        rs1 += __shfl_xor_sync(0xffffffffu, rs1, 2);
        l0 = l0 * a0 + rs0;
        l1 = l1 * a1 + rs1;
#pragma unroll
        for (int nt = 0; nt < 8; nt++) {
            o[nt][0] *= a0; o[nt][1] *= a0;
            o[nt][2] *= a1; o[nt][3] *= a1;
        }

        // ---- O += P V (x3 split; P fragments from registers) ----
#pragma unroll
        for (int kc = 0; kc < 4; kc++) {
            uint32_t ph[4], pl[4];
            split2(sc[2 * kc][0],     sc[2 * kc][1],     ph[0], pl[0]);
            split2(sc[2 * kc][2],     sc[2 * kc][3],     ph[1], pl[1]);
            split2(sc[2 * kc + 1][0], sc[2 * kc + 1][1], ph[2], pl[2]);
            split2(sc[2 * kc + 1][2], sc[2 * kc + 1][3], ph[3], pl[3]);
            uint32_t vb[16];
#pragma unroll
            for (int nb = 0; nb < 4; nb++) {
                uint32_t off = (uint32_t)(nb * 16 + rowBb) * 128 +
                               (uint32_t)(((2 * kc + chB) ^ lr) << 4);
                ldm_x4(&vb[nb * 4], sVh + off);
            }
#pragma unroll
            for (int nt = 0; nt < 8; nt++) {
                mma_16816(o[nt], ph, &vb[nt * 2]);
                mma_16816(o[nt], pl, &vb[nt * 2]);
            }
#pragma unroll
            for (int nb = 0; nb < 4; nb++) {
                uint32_t off = (uint32_t)(nb * 16 + rowBb) * 128 +
                               (uint32_t)(((2 * kc + chB) ^ lr) << 4);
                ldm_x4(&vb[nb * 4], sVl + off);
            }
#pragma unroll
            for (int nt = 0; nt < 8; nt++)
                mma_16816(o[nt], ph, &vb[nt * 2]);
        }
        __syncthreads();
    }

    // ---- normalize, split, store ctx hi/lo ----
    float inv0 = 1.0f / l0, inv1 = 1.0f / l1;
    size_t grow0 = (size_t)(b * Sz + i0 + wid * 16 + (lane >> 2)) * Dz;
    size_t grow1 = grow0 + 8 * Dz;
    int colb = h * 64 + (lane & 3) * 2;
#pragma unroll
    for (int nt = 0; nt < 8; nt++) {
        int col = colb + nt * 8;
        uint32_t h0, lo0, h1, lo1;
        split2(o[nt][0] * inv0, o[nt][1] * inv0, h0, lo0);
        split2(o[nt][2] * inv1, o[nt][3] * inv1, h1, lo1);
        *(uint32_t*)(ch + grow0 + col) = h0;
        *(uint32_t*)(cl + grow0 + col) = lo0;
        *(uint32_t*)(ch + grow1 + col) = h1;
        *(uint32_t*)(cl + grow1 + col) = lo1;
    }
}

// ==================== launch ====================
extern "C" void kernel_launch(void* const* d_in, const int* in_sizes, int n_in,
                              void* d_out, int out_size)
{
    const float* x  = (const float*)d_in[0];
    const float* Wq = (const float*)d_in[1];
    const float* bq = (const float*)d_in[2];
    const float* Wk = (const float*)d_in[3];
    const float* bk = (const float*)d_in[4];
    const float* Wv = (const float*)d_in[5];
    const float* bv = (const float*)d_in[6];
    const float* Wo = (const float*)d_in[7];
    const float* bo = (const float*)d_in[8];
    float* out = (float*)d_out;

    __nv_bfloat16 *gqh, *gql, *gkh, *gkl, *gvth, *gvtl, *gcth, *gctl, *gah, *gal, *gwth, *gwtl;
    cudaGetSymbolAddress((void**)&gqh,  g_qh);
    cudaGetSymbolAddress((void**)&gql,  g_ql);
    cudaGetSymbolAddress((void**)&gkh,  g_kh);
    cudaGetSymbolAddress((void**)&gkl,  g_kl);
    cudaGetSymbolAddress((void**)&gvth, g_vth);
    cudaGetSymbolAddress((void**)&gvtl, g_vtl);
    cudaGetSymbolAddress((void**)&gcth, g_cth);
    cudaGetSymbolAddress((void**)&gctl, g_ctl);
    cudaGetSymbolAddress((void**)&gah,  g_ah);
    cudaGetSymbolAddress((void**)&gal,  g_al);
    cudaGetSymbolAddress((void**)&gwth, g_wth);
    cudaGetSymbolAddress((void**)&gwtl, g_wtl);

    const int WSZ = Dz * Dz;
    __nv_bfloat16* wth[4] = {gwth, gwth + WSZ, gwth + 2 * WSZ, gwth + 3 * WSZ};
    __nv_bfloat16* wtl[4] = {gwtl, gwtl + WSZ, gwtl + 2 * WSZ, gwtl + 3 * WSZ};
    const float* Ws[4] = {Wq, Wk, Wv, Wo};

    split_bf16<<<Mz * Dz / 1024, 256>>>(x, gah, gal, Mz * Dz);
    for (int i = 0; i < 4; i++)
        transpose_split<<<dim3(32, 32), dim3(32, 8)>>>(Ws[i], wth[i], wtl[i]);

    size_t gsm = 3 * STAGE_BYTES + 1024;
    cudaFuncSetAttribute(gemm_hmma_x3<0>, cudaFuncAttributeMaxDynamicSharedMemorySize, (int)gsm);
    cudaFuncSetAttribute(gemm_hmma_x3<1>, cudaFuncAttributeMaxDynamicSharedMemorySize, (int)gsm);
    cudaFuncSetAttribute(gemm_hmma_x3<2>, cudaFuncAttributeMaxDynamicSharedMemorySize, (int)gsm);
    dim3 gg(Dz / 128, Mz / 128);

    // Q (pre-scaled by 1/sqrt(hd) = 0.125), K, V(transposed)
    gemm_hmma_x3<1><<<gg, 256, gsm>>>(gah, gal, wth[0], wtl[0], bq, nullptr, gqh, gql, 0.125f);
    gemm_hmma_x3<1><<<gg, 256, gsm>>>(gah, gal, wth[1], wtl[1], bk, nullptr, gkh, gkl, 1.0f);
    gemm_hmma_x3<2><<<gg, 256, gsm>>>(gah, gal, wth[2], wtl[2], bv, nullptr, gvth, gvtl, 1.0f);

    // attention
    size_t asm_ = 1024 + 32768 + 2 * 32768;   // 99328
    cudaFuncSetAttribute(flash_hmma, cudaFuncAttributeMaxDynamicSharedMemorySize, (int)asm_);
    flash_hmma<<<dim3(Sz / ABR, Bz * Hz), 256, asm_>>>(gqh, gql, gkh, gkl, gvth, gvtl, gcth, gctl);

    // output projection (fp32 out)
    gemm_hmma_x3<0><<<gg, 256, gsm>>>(gcth, gctl, wth[3], wtl[3], bo, out, nullptr, nullptr, 1.0f);
}